// round 7
// baseline (speedup 1.0000x reference)
#include <cuda_runtime.h>
#include <cuda_bf16.h>
#include <math.h>

// Problem shape (fixed by setup_inputs)
#define RB  16
#define RT  200
#define RU  100
#define RU1 101
#define RV  512
#define NEGV (-1e30f)

// Scratch — TRANSPOSED layouts for the DP phase:
//   g_blankT[b][u][t] = blank_lp[b][t][u]
//   g_emitT [b][u][t] = emit_lp [b][t][u-1]   (pre-shifted; row 0 unused)
__device__ float g_blankT[RB * RU1 * RT];
__device__ float g_emitT [RB * (RU1 + 1) * RT];
__device__ float g_costs[RB];
__device__ int   g_arrive = 0;   // self-resetting arrival counter (graph-replay safe)

// ---------------------------------------------------------------------------
// Kernel 1: per-(b,t,u) log-softmax -> blank/emit log-probs, stored transposed.
// One warp per row of V=512; 16 floats/lane in registers; MUFU exp/log.
// HBM-bound: reads 662 MB of acts exactly once, coalesced.
// ---------------------------------------------------------------------------
__global__ __launch_bounds__(256, 8)
void rnnt_lse_kernel(const float* __restrict__ acts,
                     const int*   __restrict__ labels,
                     const int*   __restrict__ label_lens)
{
    int warp = (blockIdx.x * blockDim.x + threadIdx.x) >> 5;
    int lane = threadIdx.x & 31;

    long long base = (long long)warp * RV;
    const float4* p = (const float4*)(acts + base);

    float4 v0 = p[lane +  0];
    float4 v1 = p[lane + 32];
    float4 v2 = p[lane + 64];
    float4 v3 = p[lane + 96];

    float m = fmaxf(fmaxf(fmaxf(v0.x, v0.y), fmaxf(v0.z, v0.w)),
                    fmaxf(fmaxf(v1.x, v1.y), fmaxf(v1.z, v1.w)));
    m = fmaxf(m, fmaxf(fmaxf(fmaxf(v2.x, v2.y), fmaxf(v2.z, v2.w)),
                       fmaxf(fmaxf(v3.x, v3.y), fmaxf(v3.z, v3.w))));
    #pragma unroll
    for (int o = 16; o; o >>= 1) m = fmaxf(m, __shfl_xor_sync(0xffffffffu, m, o));

    float s = 0.f;
    s += __expf(v0.x - m) + __expf(v0.y - m) + __expf(v0.z - m) + __expf(v0.w - m);
    s += __expf(v1.x - m) + __expf(v1.y - m) + __expf(v1.z - m) + __expf(v1.w - m);
    s += __expf(v2.x - m) + __expf(v2.y - m) + __expf(v2.z - m) + __expf(v2.w - m);
    s += __expf(v3.x - m) + __expf(v3.y - m) + __expf(v3.z - m) + __expf(v3.w - m);
    #pragma unroll
    for (int o = 16; o; o >>= 1) s += __shfl_xor_sync(0xffffffffu, s, o);

    if (lane == 0) {
        float lse = m + __logf(s);
        int u  = warp % RU1;
        int bt = warp / RU1;
        int t  = bt % RT;
        int b  = bt / RT;
        g_blankT[(b * RU1 + u) * RT + t] = v0.x - lse;   // acts[base+0] = BLANK
        float e = NEGV;
        if (u < label_lens[b]) {                         // label_len <= 100 < RU1
            int lab = labels[b * RU + u];                // in [1, V)
            e = acts[base + lab] - lse;
        }
        g_emitT[(b * (RU1 + 1) + (u + 1)) * RT + t] = e; // pre-shifted by one u
    }
}

// ---------------------------------------------------------------------------
// Kernel 2: anti-diagonal wavefront DP + fused final reduction.
// One CTA (128 thr) per batch; thread u owns lattice column u. With the
// transposed layout, each thread's blank/emit loads advance +4B per diagonal
// -> L1-resident (1 miss per 32 iters). Neighbor alpha via __shfl_up;
// cross-warp boundary via dbl-buffered SMEM; ONE barrier per diagonal.
// ---------------------------------------------------------------------------
__device__ __forceinline__ float laexp(float x, float y)
{
    float m = fmaxf(x, y);
    float d = fabsf(x - y);
    return m + __logf(1.f + __expf(-d));
}

__global__ __launch_bounds__(128, 1)
void rnnt_alpha_kernel(const int* __restrict__ act_lens,
                       const int* __restrict__ label_lens,
                       float* __restrict__ out)
{
    const int b    = blockIdx.x;
    const int tid  = threadIdx.x;
    const int w    = tid >> 5;
    const int lane = tid & 31;
    const int u    = tid;                      // threads 101..127 are passengers
    const int uc   = min(u, RU1 - 1);

    // per-thread row pointers (transposed layout)
    const float* __restrict__ blkRow = g_blankT + (b * RU1 + uc) * RT;        // blank[.][uc]
    const float* __restrict__ emtRow = g_emitT  + (b * (RU1 + 1) + uc) * RT;  // emit[.][uc-1]

    const int aT   = act_lens[b];
    const int L    = label_lens[b];
    const int dmax = aT - 1 + L;               // diag of terminal cell

    __shared__ float sbnd[2][4];               // per-warp boundary alpha, dbl-buffered
    if (tid < 8) sbnd[tid >> 2][tid & 3] = NEGV;

    // depth-2 operand pipeline: slot k holds (bl, em) for diagonal d with d&1==k
    float blq[2], emq[2];
    #pragma unroll
    for (int k = 0; k < 2; ++k) {
        int t  = k - uc;
        int tb = min(max(t - 1, 0), RT - 1);
        int te = min(max(t,     0), RT - 1);
        blq[k] = blkRow[tb];                   // blank[t-1][uc]
        emq[k] = emtRow[te];                   // emit [t][uc-1]
    }

    float a = NEGV;                            // alpha at previous diagonal, this u
    int   p = 0;
    __syncthreads();

    for (int d = 0; d <= dmax; ++d) {
        const int slot = d & 1;
        const float bl = blq[slot], em = emq[slot];

        // issue loads for diagonal d+2 immediately (L1 hits ~31/32 of the time)
        {
            int t  = d + 2 - uc;
            int tb = min(max(t - 1, 0), RT - 1);
            int te = min(max(t,     0), RT - 1);
            blq[slot] = blkRow[tb];
            emq[slot] = emtRow[te];
        }

        // alpha(prev diag, u-1): intra-warp shuffle; lane0 from left warp's slot
        float a_left = __shfl_up_sync(0xffffffffu, a, 1);
        if (lane == 0) a_left = (w > 0) ? sbnd[p][w - 1] : NEGV;

        const int t = d - u;
        const bool active = (u < RU1) & (t >= 0) & (t < RT);
        float noemit = (t >= 1) ? (a + bl)      : NEGV;
        float emitv  = (u >= 1) ? (a_left + em) : NEGV;
        float anew = laexp(noemit, emitv);
        if (t == 0 && u == 0) anew = 0.f;

        if (active) {
            a = anew;
            if (t == aT - 1 && u == L)
                g_costs[b] = -(a + blkRow[t]);  // + blank_lp[aT-1][L]
        }
        if (lane == 31) sbnd[p ^ 1][w] = a;    // publish boundary for next diag
        __syncthreads();
        p ^= 1;
    }

    // fused deterministic reduction (threadfence-reduction pattern)
    __syncthreads();
    if (tid == 0) {
        __threadfence();
        int prev = atomicAdd(&g_arrive, 1);
        if (prev == RB - 1) {
            atomicExch(&g_arrive, 0);          // reset for next graph replay
            __threadfence();
            float s = 0.f;
            #pragma unroll
            for (int i = 0; i < RB; ++i) s += g_costs[i];
            out[0] = s * (1.0f / RB);
        }
    }
}

extern "C" void kernel_launch(void* const* d_in, const int* in_sizes, int n_in,
                              void* d_out, int out_size)
{
    const float* acts       = (const float*)d_in[0];
    const int*   labels     = (const int*)  d_in[1];
    const int*   act_lens   = (const int*)  d_in[2];
    const int*   label_lens = (const int*)  d_in[3];
    float*       out        = (float*)      d_out;

    const int rows   = RB * RT * RU1;              // 323200 rows, 1 warp each
    const int blocks = rows / 8;                   // 8 warps per 256-thr block (exact)

    rnnt_lse_kernel<<<blocks, 256>>>(acts, labels, label_lens);
    rnnt_alpha_kernel<<<RB, 128>>>(act_lens, label_lens, out);
}